// round 3
// baseline (speedup 1.0000x reference)
#include <cuda_runtime.h>

// NCC2D: -mean( cross^2 / (I_var*J_var + 1e-5) ), 9x9 zero-padded box sums.
// cross = IJ - I*J/81 ; I_var = I2 - I^2/81 ; J_var = J2 - J^2/81.
//
// Fused single kernel:
//   grid = (2, 8, 32), 64 threads/block, 4 cols/thread (float4 groups).
//   Per ingested row each thread loads ONLY its own float4 per input; the
//   left/right neighbor float4s come from warp shuffles (lanes 0/31 patch via
//   one predicated LDG each). Horizontal 9-tap via register sliding window,
//   vertical via running sums + 9-deep smem ring of horizontal sums.
//   Block partial -> double atomic; last block finalizes and resets state.

#define BW   512
#define BH   512
#define NB   32
#define ROWS 64
#define TPB  64
#define NVEC 128
#define NBLOCKS (2 * 8 * 32)

__device__ double       g_acc;   // zero-init at load; reset by last block
__device__ unsigned int g_cnt;

__device__ __forceinline__ float4 shfl_up4(float4 v) {
    float4 r;
    r.x = __shfl_up_sync(0xffffffffu, v.x, 1);
    r.y = __shfl_up_sync(0xffffffffu, v.y, 1);
    r.z = __shfl_up_sync(0xffffffffu, v.z, 1);
    r.w = __shfl_up_sync(0xffffffffu, v.w, 1);
    return r;
}
__device__ __forceinline__ float4 shfl_dn4(float4 v) {
    float4 r;
    r.x = __shfl_down_sync(0xffffffffu, v.x, 1);
    r.y = __shfl_down_sync(0xffffffffu, v.y, 1);
    r.z = __shfl_down_sync(0xffffffffu, v.z, 1);
    r.w = __shfl_down_sync(0xffffffffu, v.w, 1);
    return r;
}

__global__ __launch_bounds__(TPB) void ncc_main_k(const float* __restrict__ gI,
                                                  const float* __restrict__ gJ,
                                                  float* __restrict__ out) {
    __shared__ float4 ring[9 * 5 * TPB];   // [slot][product][thread] = 46080 B
    __shared__ float  wsum[TPB / 32];

    const int t    = threadIdx.x;
    const int lane = t & 31;
    const int vb   = blockIdx.x * TPB + t;         // float4 index in the row
    const int r0   = blockIdx.y * ROWS;
    const size_t img = (size_t)blockIdx.z * ((size_t)BH * BW);

    const bool needPrevLd = (lane == 0)  && (vb != 0);         // patch via LDG
    const bool needNextLd = (lane == 31) && (vb != NVEC - 1);

#pragma unroll
    for (int s = 0; s < 9; ++s)
#pragma unroll
        for (int p = 0; p < 5; ++p)
            ring[(s * 5 + p) * TPB + t] = make_float4(0.f, 0.f, 0.f, 0.f);

    float S[5][4];
#pragma unroll
    for (int p = 0; p < 5; ++p)
#pragma unroll
        for (int c = 0; c < 4; ++c) S[p][c] = 0.f;

    float acc = 0.f;
    const float inv81 = 1.0f / 81.0f;
    const float4 z = make_float4(0.f, 0.f, 0.f, 0.f);

    for (int base = 0; base < ROWS + 8; base += 9) {
#pragma unroll
        for (int s = 0; s < 9; ++s) {
            const int r = r0 - 4 + base + s;
            float h[5][4];
            if (r >= 0 && r < BH) {
                const float4* pI = (const float4*)(gI + img + (size_t)r * BW);
                const float4* pJ = (const float4*)(gJ + img + (size_t)r * BW);
                float4 a1 = __ldg(pI + vb);
                float4 b1 = __ldg(pJ + vb);
                // Neighbor float4s: warp shuffle; edge lanes patch from gmem.
                float4 a0 = shfl_up4(a1);
                float4 b0 = shfl_up4(b1);
                float4 a2 = shfl_dn4(a1);
                float4 b2 = shfl_dn4(b1);
                if (lane == 0)  { a0 = needPrevLd ? __ldg(pI + vb - 1) : z;
                                  b0 = needPrevLd ? __ldg(pJ + vb - 1) : z; }
                if (lane == 31) { a2 = needNextLd ? __ldg(pI + vb + 1) : z;
                                  b2 = needNextLd ? __ldg(pJ + vb + 1) : z; }

                float av[12] = {a0.x, a0.y, a0.z, a0.w, a1.x, a1.y, a1.z, a1.w,
                                a2.x, a2.y, a2.z, a2.w};
                float bv[12] = {b0.x, b0.y, b0.z, b0.w, b1.x, b1.y, b1.z, b1.w,
                                b2.x, b2.y, b2.z, b2.w};
                float qa[12], qb[12], qc[12];
#pragma unroll
                for (int i = 0; i < 12; ++i) {
                    qa[i] = av[i] * av[i];
                    qb[i] = bv[i] * bv[i];
                    qc[i] = av[i] * bv[i];
                }
                float sI = 0.f, sJ = 0.f, sI2 = 0.f, sJ2 = 0.f, sIJ = 0.f;
#pragma unroll
                for (int k = 0; k < 9; ++k) {
                    sI += av[k]; sJ += bv[k]; sI2 += qa[k]; sJ2 += qb[k]; sIJ += qc[k];
                }
                h[0][0] = sI; h[1][0] = sJ; h[2][0] = sI2; h[3][0] = sJ2; h[4][0] = sIJ;
#pragma unroll
                for (int c = 1; c < 4; ++c) {
                    h[0][c] = h[0][c - 1] - av[c - 1] + av[c + 8];
                    h[1][c] = h[1][c - 1] - bv[c - 1] + bv[c + 8];
                    h[2][c] = h[2][c - 1] - qa[c - 1] + qa[c + 8];
                    h[3][c] = h[3][c - 1] - qb[c - 1] + qb[c + 8];
                    h[4][c] = h[4][c - 1] - qc[c - 1] + qc[c + 8];
                }
            } else {
#pragma unroll
                for (int p = 0; p < 5; ++p)
#pragma unroll
                    for (int c = 0; c < 4; ++c) h[p][c] = 0.f;
            }

#pragma unroll
            for (int p = 0; p < 5; ++p) {
                float4* slot = &ring[(s * 5 + p) * TPB + t];
                float4 old = *slot;
                S[p][0] += h[p][0] - old.x;
                S[p][1] += h[p][1] - old.y;
                S[p][2] += h[p][2] - old.z;
                S[p][3] += h[p][3] - old.w;
                *slot = make_float4(h[p][0], h[p][1], h[p][2], h[p][3]);
            }

            if (r >= r0 + 4) {
#pragma unroll
                for (int c = 0; c < 4; ++c) {
                    float sI = S[0][c], sJ = S[1][c];
                    float cross = fmaf(sI * sJ, -inv81, S[4][c]);
                    float Iv    = fmaf(sI * sI, -inv81, S[2][c]);
                    float Jv    = fmaf(sJ * sJ, -inv81, S[3][c]);
                    float den   = fmaf(Iv, Jv, 1e-5f);
                    acc += __fdividef(cross * cross, den);
                }
            }
        }
    }

    // Block reduction -> global double atomic; last block finalizes + resets.
#pragma unroll
    for (int o = 16; o; o >>= 1) acc += __shfl_xor_sync(0xffffffffu, acc, o);
    if (lane == 0) wsum[t >> 5] = acc;
    __syncthreads();
    if (t == 0) {
        float bs = 0.f;
#pragma unroll
        for (int w = 0; w < TPB / 32; ++w) bs += wsum[w];
        atomicAdd(&g_acc, (double)bs);
        __threadfence();
        unsigned int done = atomicAdd(&g_cnt, 1u);
        if (done == NBLOCKS - 1) {
            __threadfence();
            double v = *((volatile double*)&g_acc);
            out[0] = (float)(-v * (1.0 / (double)((long long)NB * BH * BW)));
            g_acc = 0.0;          // reset for next graph replay
            g_cnt = 0u;
        }
    }
}

extern "C" void kernel_launch(void* const* d_in, const int* in_sizes, int n_in,
                              void* d_out, int out_size) {
    const float* I = (const float*)d_in[0];
    const float* J = (const float*)d_in[1];
    float* out = (float*)d_out;

    dim3 grid(NVEC / TPB, BH / ROWS, NB);   // (2, 8, 32) = 512 blocks
    ncc_main_k<<<grid, TPB>>>(I, J, out);
}

// round 4
// speedup vs baseline: 1.0338x; 1.0338x over previous
#include <cuda_runtime.h>

// NCC2D: -mean( cross^2 / (I_var*J_var + 1e-5) ), 9x9 zero-padded box sums.
// cross = IJ - I*J/81 ; I_var = I2 - I^2/81 ; J_var = J2 - J^2/81.
//
// Fused single kernel, latency-optimized:
//   grid (2,16,32) = 1024 blocks, 64 thr/block, 4 cols/thread (float4).
//   Direct LDG.128 halo loads (no shuffles), branchless row clamp+mask so the
//   9x-unrolled body is straight-line (load batching / high MLP).
//   Horizontal 9-tap sliding windows (FFMA-fused for I2/J2/IJ).
//   Vertical running sums; sI ring in REGISTERS, 4 product rings in smem
//   (36.9 KB -> 6 blocks/SM = 12 warps, vs 8 before).
//   Block partial -> double atomic; last block finalizes + resets (graph-safe).

#define BW   512
#define BH   512
#define NB   32
#define ROWS 32
#define TPB  64
#define NVEC 128
#define GRIDY (BH / ROWS)
#define NBLOCKS ((NVEC / TPB) * GRIDY * NB)

__device__ double       g_acc;   // zero-init at load; reset by last block
__device__ unsigned int g_cnt;

__global__ __launch_bounds__(TPB) void ncc_main_k(const float* __restrict__ gI,
                                                  const float* __restrict__ gJ,
                                                  float* __restrict__ out) {
    __shared__ float4 ring[9 * 4 * TPB];   // products sJ,sI2,sJ2,sIJ : 36864 B
    __shared__ float  wsum[TPB / 32];

    const int t    = threadIdx.x;
    const int lane = t & 31;
    const int vb   = blockIdx.x * TPB + t;         // float4 index in the row
    const int r0   = blockIdx.y * ROWS;
    const size_t img = (size_t)blockIdx.z * ((size_t)BH * BW);

    const bool leftEdge  = (vb == 0);
    const bool rightEdge = (vb == NVEC - 1);

    float ringI[9][4];                              // sI ring in registers
#pragma unroll
    for (int s = 0; s < 9; ++s)
#pragma unroll
        for (int c = 0; c < 4; ++c) ringI[s][c] = 0.f;
#pragma unroll
    for (int s = 0; s < 9; ++s)
#pragma unroll
        for (int p = 0; p < 4; ++p)
            ring[(s * 4 + p) * TPB + t] = make_float4(0.f, 0.f, 0.f, 0.f);

    float S[5][4];
#pragma unroll
    for (int p = 0; p < 5; ++p)
#pragma unroll
        for (int c = 0; c < 4; ++c) S[p][c] = 0.f;

    float acc = 0.f;
    const float inv81 = 1.0f / 81.0f;
    const float4 z = make_float4(0.f, 0.f, 0.f, 0.f);

    for (int base = 0; base < ROWS + 8; base += 9) {
#pragma unroll
        for (int s = 0; s < 9; ++s) {
            if (base + s < ROWS + 8) {
                const int r  = r0 - 4 + base + s;
                const int rc = min(max(r, 0), BH - 1);         // clamp row
                const float m = (r >= 0 && r < BH) ? 1.f : 0.f; // zero-pad mask

                const float4* pI = (const float4*)(gI + img + (size_t)rc * BW);
                const float4* pJ = (const float4*)(gJ + img + (size_t)rc * BW);
                float4 a1 = __ldg(pI + vb);
                float4 b1 = __ldg(pJ + vb);
                float4 a0 = leftEdge  ? z : __ldg(pI + vb - 1);
                float4 a2 = rightEdge ? z : __ldg(pI + vb + 1);
                float4 b0 = leftEdge  ? z : __ldg(pJ + vb - 1);
                float4 b2 = rightEdge ? z : __ldg(pJ + vb + 1);

                float av[12] = {a0.x, a0.y, a0.z, a0.w, a1.x, a1.y, a1.z, a1.w,
                                a2.x, a2.y, a2.z, a2.w};
                float bv[12] = {b0.x, b0.y, b0.z, b0.w, b1.x, b1.y, b1.z, b1.w,
                                b2.x, b2.y, b2.z, b2.w};

                float h[5][4];
                // sI, sJ: plain sliding windows (8 + 6 adds each)
                {
                    float w = ((av[0] + av[1]) + (av[2] + av[3]))
                            + ((av[4] + av[5]) + (av[6] + av[7])) + av[8];
                    h[0][0] = w;
                    h[0][1] = w = w - av[0] + av[9];
                    h[0][2] = w = w - av[1] + av[10];
                    h[0][3] =     w - av[2] + av[11];
                }
                {
                    float w = ((bv[0] + bv[1]) + (bv[2] + bv[3]))
                            + ((bv[4] + bv[5]) + (bv[6] + bv[7])) + bv[8];
                    h[1][0] = w;
                    h[1][1] = w = w - bv[0] + bv[9];
                    h[1][2] = w = w - bv[1] + bv[10];
                    h[1][3] =     w - bv[2] + bv[11];
                }
                // sI2: FFMA-fused window + slides
                {
                    float q0 = av[0] * av[0];
                    float w  = q0;
#pragma unroll
                    for (int k = 1; k < 9; ++k) w = fmaf(av[k], av[k], w);
                    float q1 = av[1] * av[1];
                    float q2 = av[2] * av[2];
                    h[2][0] = w;
                    h[2][1] = w = fmaf(av[9],  av[9],  w - q0);
                    h[2][2] = w = fmaf(av[10], av[10], w - q1);
                    h[2][3] =     fmaf(av[11], av[11], w - q2);
                }
                // sJ2
                {
                    float q0 = bv[0] * bv[0];
                    float w  = q0;
#pragma unroll
                    for (int k = 1; k < 9; ++k) w = fmaf(bv[k], bv[k], w);
                    float q1 = bv[1] * bv[1];
                    float q2 = bv[2] * bv[2];
                    h[3][0] = w;
                    h[3][1] = w = fmaf(bv[9],  bv[9],  w - q0);
                    h[3][2] = w = fmaf(bv[10], bv[10], w - q1);
                    h[3][3] =     fmaf(bv[11], bv[11], w - q2);
                }
                // sIJ
                {
                    float q0 = av[0] * bv[0];
                    float w  = q0;
#pragma unroll
                    for (int k = 1; k < 9; ++k) w = fmaf(av[k], bv[k], w);
                    float q1 = av[1] * bv[1];
                    float q2 = av[2] * bv[2];
                    h[4][0] = w;
                    h[4][1] = w = fmaf(av[9],  bv[9],  w - q0);
                    h[4][2] = w = fmaf(av[10], bv[10], w - q1);
                    h[4][3] =     fmaf(av[11], bv[11], w - q2);
                }
                // zero-pad mask (out-of-range rows contribute nothing)
#pragma unroll
                for (int p = 0; p < 5; ++p)
#pragma unroll
                    for (int c = 0; c < 4; ++c) h[p][c] *= m;

                // vertical running sums: sI via register ring
#pragma unroll
                for (int c = 0; c < 4; ++c) {
                    S[0][c] += h[0][c] - ringI[s][c];
                    ringI[s][c] = h[0][c];
                }
                // products 1..4 via smem ring
#pragma unroll
                for (int p = 1; p < 5; ++p) {
                    float4* slot = &ring[(s * 4 + (p - 1)) * TPB + t];
                    float4 old = *slot;
                    S[p][0] += h[p][0] - old.x;
                    S[p][1] += h[p][1] - old.y;
                    S[p][2] += h[p][2] - old.z;
                    S[p][3] += h[p][3] - old.w;
                    *slot = make_float4(h[p][0], h[p][1], h[p][2], h[p][3]);
                }

                if (r >= r0 + 4) {   // output row r-4 complete
#pragma unroll
                    for (int c = 0; c < 4; ++c) {
                        float sI = S[0][c], sJ = S[1][c];
                        float cross = fmaf(sI * sJ, -inv81, S[4][c]);
                        float Iv    = fmaf(sI * sI, -inv81, S[2][c]);
                        float Jv    = fmaf(sJ * sJ, -inv81, S[3][c]);
                        float den   = fmaf(Iv, Jv, 1e-5f);
                        acc += __fdividef(cross * cross, den);
                    }
                }
            }
        }
    }

    // Block reduction -> global double atomic; last block finalizes + resets.
#pragma unroll
    for (int o = 16; o; o >>= 1) acc += __shfl_xor_sync(0xffffffffu, acc, o);
    if (lane == 0) wsum[t >> 5] = acc;
    __syncthreads();
    if (t == 0) {
        float bs = 0.f;
#pragma unroll
        for (int w = 0; w < TPB / 32; ++w) bs += wsum[w];
        atomicAdd(&g_acc, (double)bs);
        __threadfence();
        unsigned int done = atomicAdd(&g_cnt, 1u);
        if (done == NBLOCKS - 1) {
            __threadfence();
            double v = *((volatile double*)&g_acc);
            out[0] = (float)(-v * (1.0 / (double)((long long)NB * BH * BW)));
            g_acc = 0.0;          // reset for next graph replay
            g_cnt = 0u;
        }
    }
}

extern "C" void kernel_launch(void* const* d_in, const int* in_sizes, int n_in,
                              void* d_out, int out_size) {
    const float* I = (const float*)d_in[0];
    const float* J = (const float*)d_in[1];
    float* out = (float*)d_out;

    dim3 grid(NVEC / TPB, GRIDY, NB);   // (2, 16, 32) = 1024 blocks
    ncc_main_k<<<grid, TPB>>>(I, J, out);
}

// round 5
// speedup vs baseline: 1.2103x; 1.1707x over previous
#include <cuda_runtime.h>

// NCC2D: -mean( cross^2 / (I_var*J_var + 1e-5) ), 9x9 zero-padded box sums.
// cross = IJ - I*J/81 ; I_var = I2 - I^2/81 ; J_var = J2 - J^2/81.
//
// Fused single kernel, issue/latency-optimized:
//   grid (2,16,32)=1024 blocks, 64 thr/block, 4 cols/thread (float4).
//   LEAN branchy ingest (round-1 style: skip loads+compute out of range).
//   Horizontal 9-tap sliding windows (FFMA-fused products).
//   Vertical running sums; sI ring in registers, 4 product rings in smem
//   (36.9KB -> 6 blocks/SM; ~12 warps/SM resident).
//   Block partial -> double atomic; last block finalizes + resets (graph-safe).

#define BW   512
#define BH   512
#define NB   32
#define ROWS 32
#define TPB  64
#define NVEC 128
#define GRIDY (BH / ROWS)
#define NBLOCKS ((NVEC / TPB) * GRIDY * NB)

__device__ double       g_acc;   // zero-init at load; reset by last block
__device__ unsigned int g_cnt;

__global__ __launch_bounds__(TPB) void ncc_main_k(const float* __restrict__ gI,
                                                  const float* __restrict__ gJ,
                                                  float* __restrict__ out) {
    __shared__ float4 ring[9 * 4 * TPB];   // sJ,sI2,sJ2,sIJ rings : 36864 B
    __shared__ float  wsum[TPB / 32];

    const int t    = threadIdx.x;
    const int lane = t & 31;
    const int vb   = blockIdx.x * TPB + t;         // float4 index in the row
    const int r0   = blockIdx.y * ROWS;
    const size_t img = (size_t)blockIdx.z * ((size_t)BH * BW);

    const bool leftEdge  = (vb == 0);
    const bool rightEdge = (vb == NVEC - 1);

    float ringI[9][4];                              // sI ring in registers
#pragma unroll
    for (int s = 0; s < 9; ++s)
#pragma unroll
        for (int c = 0; c < 4; ++c) ringI[s][c] = 0.f;
#pragma unroll
    for (int s = 0; s < 9; ++s)
#pragma unroll
        for (int p = 0; p < 4; ++p)
            ring[(s * 4 + p) * TPB + t] = make_float4(0.f, 0.f, 0.f, 0.f);

    float S[5][4];
#pragma unroll
    for (int p = 0; p < 5; ++p)
#pragma unroll
        for (int c = 0; c < 4; ++c) S[p][c] = 0.f;

    float acc = 0.f;
    const float inv81 = 1.0f / 81.0f;
    const float4 z = make_float4(0.f, 0.f, 0.f, 0.f);

    // One ingest step: row r with ring slot s. Branchy (lean): out-of-range
    // rows skip loads/compute and push zeros through the rings.
#define INGEST(SLOT, LI)                                                        \
    {                                                                           \
        const int r = r0 - 4 + (LI);                                            \
        float h[5][4];                                                          \
        if (r >= 0 && r < BH) {                                                 \
            const float4* pI = (const float4*)(gI + img + (size_t)r * BW);      \
            const float4* pJ = (const float4*)(gJ + img + (size_t)r * BW);      \
            float4 a1 = __ldg(pI + vb);                                         \
            float4 b1 = __ldg(pJ + vb);                                         \
            float4 a0 = leftEdge  ? z : __ldg(pI + vb - 1);                     \
            float4 a2 = rightEdge ? z : __ldg(pI + vb + 1);                     \
            float4 b0 = leftEdge  ? z : __ldg(pJ + vb - 1);                     \
            float4 b2 = rightEdge ? z : __ldg(pJ + vb + 1);                     \
            float av[12] = {a0.x, a0.y, a0.z, a0.w, a1.x, a1.y, a1.z, a1.w,     \
                            a2.x, a2.y, a2.z, a2.w};                            \
            float bv[12] = {b0.x, b0.y, b0.z, b0.w, b1.x, b1.y, b1.z, b1.w,     \
                            b2.x, b2.y, b2.z, b2.w};                            \
            {   float w = ((av[0] + av[1]) + (av[2] + av[3]))                   \
                        + ((av[4] + av[5]) + (av[6] + av[7])) + av[8];          \
                h[0][0] = w;                                                    \
                h[0][1] = w = w - av[0] + av[9];                                \
                h[0][2] = w = w - av[1] + av[10];                               \
                h[0][3] =     w - av[2] + av[11]; }                             \
            {   float w = ((bv[0] + bv[1]) + (bv[2] + bv[3]))                   \
                        + ((bv[4] + bv[5]) + (bv[6] + bv[7])) + bv[8];          \
                h[1][0] = w;                                                    \
                h[1][1] = w = w - bv[0] + bv[9];                                \
                h[1][2] = w = w - bv[1] + bv[10];                               \
                h[1][3] =     w - bv[2] + bv[11]; }                             \
            {   float q0 = av[0] * av[0];                                       \
                float w  = q0;                                                  \
                _Pragma("unroll")                                               \
                for (int k = 1; k < 9; ++k) w = fmaf(av[k], av[k], w);          \
                float q1 = av[1] * av[1];                                       \
                float q2 = av[2] * av[2];                                       \
                h[2][0] = w;                                                    \
                h[2][1] = w = fmaf(av[9],  av[9],  w - q0);                     \
                h[2][2] = w = fmaf(av[10], av[10], w - q1);                     \
                h[2][3] =     fmaf(av[11], av[11], w - q2); }                   \
            {   float q0 = bv[0] * bv[0];                                       \
                float w  = q0;                                                  \
                _Pragma("unroll")                                               \
                for (int k = 1; k < 9; ++k) w = fmaf(bv[k], bv[k], w);          \
                float q1 = bv[1] * bv[1];                                       \
                float q2 = bv[2] * bv[2];                                       \
                h[3][0] = w;                                                    \
                h[3][1] = w = fmaf(bv[9],  bv[9],  w - q0);                     \
                h[3][2] = w = fmaf(bv[10], bv[10], w - q1);                     \
                h[3][3] =     fmaf(bv[11], bv[11], w - q2); }                   \
            {   float q0 = av[0] * bv[0];                                       \
                float w  = q0;                                                  \
                _Pragma("unroll")                                               \
                for (int k = 1; k < 9; ++k) w = fmaf(av[k], bv[k], w);          \
                float q1 = av[1] * bv[1];                                       \
                float q2 = av[2] * bv[2];                                       \
                h[4][0] = w;                                                    \
                h[4][1] = w = fmaf(av[9],  bv[9],  w - q0);                     \
                h[4][2] = w = fmaf(av[10], bv[10], w - q1);                     \
                h[4][3] =     fmaf(av[11], bv[11], w - q2); }                   \
        } else {                                                                \
            _Pragma("unroll")                                                   \
            for (int p = 0; p < 5; ++p)                                         \
                _Pragma("unroll")                                               \
                for (int c = 0; c < 4; ++c) h[p][c] = 0.f;                      \
        }                                                                       \
        _Pragma("unroll")                                                       \
        for (int c = 0; c < 4; ++c) {                                           \
            S[0][c] += h[0][c] - ringI[SLOT][c];                                \
            ringI[SLOT][c] = h[0][c];                                           \
        }                                                                       \
        _Pragma("unroll")                                                       \
        for (int p = 1; p < 5; ++p) {                                           \
            float4* slot = &ring[((SLOT) * 4 + (p - 1)) * TPB + t];             \
            float4 old = *slot;                                                 \
            S[p][0] += h[p][0] - old.x;                                         \
            S[p][1] += h[p][1] - old.y;                                         \
            S[p][2] += h[p][2] - old.z;                                         \
            S[p][3] += h[p][3] - old.w;                                         \
            *slot = make_float4(h[p][0], h[p][1], h[p][2], h[p][3]);            \
        }                                                                       \
        if ((LI) >= 8) {                                                        \
            _Pragma("unroll")                                                   \
            for (int c = 0; c < 4; ++c) {                                       \
                float sI = S[0][c], sJ = S[1][c];                               \
                float cross = fmaf(sI * sJ, -inv81, S[4][c]);                   \
                float Iv    = fmaf(sI * sI, -inv81, S[2][c]);                   \
                float Jv    = fmaf(sJ * sJ, -inv81, S[3][c]);                   \
                float den   = fmaf(Iv, Jv, 1e-5f);                              \
                acc += __fdividef(cross * cross, den);                          \
            }                                                                   \
        }                                                                       \
    }

    // 40 ingest rows = 4 full chunks of 9 (+ explicit 4-row tail, slots 0..3).
    for (int base = 0; base < 36; base += 9) {
#pragma unroll
        for (int s = 0; s < 9; ++s) INGEST(s, base + s)
    }
#pragma unroll
    for (int s = 0; s < 4; ++s) INGEST(s, 36 + s)
#undef INGEST

    // Block reduction -> global double atomic; last block finalizes + resets.
#pragma unroll
    for (int o = 16; o; o >>= 1) acc += __shfl_xor_sync(0xffffffffu, acc, o);
    if (lane == 0) wsum[t >> 5] = acc;
    __syncthreads();
    if (t == 0) {
        float bs = 0.f;
#pragma unroll
        for (int w = 0; w < TPB / 32; ++w) bs += wsum[w];
        atomicAdd(&g_acc, (double)bs);
        __threadfence();
        unsigned int done = atomicAdd(&g_cnt, 1u);
        if (done == NBLOCKS - 1) {
            __threadfence();
            double v = *((volatile double*)&g_acc);
            out[0] = (float)(-v * (1.0 / (double)((long long)NB * BH * BW)));
            g_acc = 0.0;          // reset for next graph replay
            g_cnt = 0u;
        }
    }
}

extern "C" void kernel_launch(void* const* d_in, const int* in_sizes, int n_in,
                              void* d_out, int out_size) {
    const float* I = (const float*)d_in[0];
    const float* J = (const float*)d_in[1];
    float* out = (float*)d_out;

    dim3 grid(NVEC / TPB, GRIDY, NB);   // (2, 16, 32) = 1024 blocks
    ncc_main_k<<<grid, TPB>>>(I, J, out);
}

// round 7
// speedup vs baseline: 1.6998x; 1.4045x over previous
#include <cuda_runtime.h>

// NCC2D: -mean( cross^2 / (I_var*J_var + 1e-5) ), 9x9 zero-padded box sums.
// cross = IJ - I*J/81 ; I_var = I2 - I^2/81 ; J_var = J2 - J^2/81.
//
// Ring-free vertical-first formulation:
//   grid (22 strips, 32 images), TPB=128 (one full 512-col row, 4 cols/thr).
//   Per ingested row: load own float4 of I,J at row rn (new) and rn-9 (old,
//   L1/L2 hit), update per-column vertical running sums V_p in registers.
//   FIX vs round 6: subtract the old row ONLY when it was actually added
//   (it >= 9) — previously warm-up iterations subtracted rows never added.
//   Emit rows write V to a double-buffered smem row (20KB), 1 bar, read
//   neighbor V, 9-tap horizontal window -> 9x9 box sums -> NCC term.
//   5 blocks/SM * 4 warps = 20 warps/SM, single wave (704 <= 740 resident).
//   Block partial -> double atomic; last block finalizes + resets.

#define BW   512
#define BH   512
#define NB   32
#define ROWS 24
#define TPB  128
#define STRIPS 22                    // 21 full strips of 24 + one of 8
#define NBLOCKS (STRIPS * NB)        // 704

__device__ double       g_acc;   // zero-init at load; reset by last block
__device__ unsigned int g_cnt;

__global__ __launch_bounds__(TPB, 5) void ncc_main_k(const float* __restrict__ gI,
                                                     const float* __restrict__ gJ,
                                                     float* __restrict__ out) {
    __shared__ float4 sV[2][5][TPB];     // double-buffered V exchange: 20480 B
    __shared__ float  wsum[TPB / 32];

    const int t    = threadIdx.x;
    const int lane = t & 31;
    const int r0   = blockIdx.x * ROWS;
    const int rows_eff = min(ROWS, BH - r0);
    const size_t img = (size_t)blockIdx.y * ((size_t)BH * BW);
    const float4 z = make_float4(0.f, 0.f, 0.f, 0.f);
    const float inv81 = 1.0f / 81.0f;

    float vI[4]  = {0.f, 0.f, 0.f, 0.f};
    float vJ[4]  = {0.f, 0.f, 0.f, 0.f};
    float vI2[4] = {0.f, 0.f, 0.f, 0.f};
    float vJ2[4] = {0.f, 0.f, 0.f, 0.f};
    float vIJ[4] = {0.f, 0.f, 0.f, 0.f};
    float acc = 0.f;

    const int iters = rows_eff + 8;
#pragma unroll 2
    for (int it = 0; it < iters; ++it) {
        const int rn = r0 - 4 + it;      // new row entering the window
        const int ro = rn - 9;           // old row leaving the window

        float4 a1 = z, b1 = z, ao = z, bo = z;
        if (rn >= 0 && rn < BH) {
            a1 = __ldg((const float4*)(gI + img + (size_t)rn * BW) + t);
            b1 = __ldg((const float4*)(gJ + img + (size_t)rn * BW) + t);
        }
        // Old row must have been ADDED earlier (it >= 9) and be a real row.
        if (it >= 9 && ro >= 0) {
            ao = __ldg((const float4*)(gI + img + (size_t)ro * BW) + t);
            bo = __ldg((const float4*)(gJ + img + (size_t)ro * BW) + t);
        }
        const float an[4] = {a1.x, a1.y, a1.z, a1.w};
        const float bn[4] = {b1.x, b1.y, b1.z, b1.w};
        const float ap[4] = {ao.x, ao.y, ao.z, ao.w};
        const float bp[4] = {bo.x, bo.y, bo.z, bo.w};
#pragma unroll
        for (int c = 0; c < 4; ++c) {
            vI[c] += an[c] - ap[c];
            vJ[c] += bn[c] - bp[c];
            vI2[c] = fmaf(an[c], an[c], fmaf(-ap[c], ap[c], vI2[c]));
            vJ2[c] = fmaf(bn[c], bn[c], fmaf(-bp[c], bp[c], vJ2[c]));
            vIJ[c] = fmaf(an[c], bn[c], fmaf(-ap[c], bp[c], vIJ[c]));
        }

        if (it >= 8) {                   // output row y = rn - 4 is complete
            const int buf = it & 1;
            sV[buf][0][t] = make_float4(vI[0],  vI[1],  vI[2],  vI[3]);
            sV[buf][1][t] = make_float4(vJ[0],  vJ[1],  vJ[2],  vJ[3]);
            sV[buf][2][t] = make_float4(vI2[0], vI2[1], vI2[2], vI2[3]);
            sV[buf][3][t] = make_float4(vJ2[0], vJ2[1], vJ2[2], vJ2[3]);
            sV[buf][4][t] = make_float4(vIJ[0], vIJ[1], vIJ[2], vIJ[3]);
            __syncthreads();

            float box[5][4];
#define DO_WIN(P, VA)                                                          \
            {                                                                  \
                float4 L = (t > 0)       ? sV[buf][P][t - 1] : z;              \
                float4 R = (t < TPB - 1) ? sV[buf][P][t + 1] : z;              \
                float v0 = L.x, v1 = L.y, v2 = L.z, v3 = L.w;                  \
                float v4 = VA[0], v5 = VA[1], v6 = VA[2], v7 = VA[3];          \
                float v8 = R.x, v9 = R.y, v10 = R.z, v11 = R.w;                \
                float w = ((v0 + v1) + (v2 + v3))                              \
                        + ((v4 + v5) + (v6 + v7)) + v8;                        \
                box[P][0] = w;                                                 \
                box[P][1] = w = w - v0 + v9;                                   \
                box[P][2] = w = w - v1 + v10;                                  \
                box[P][3] =     w - v2 + v11;                                  \
            }
            DO_WIN(0, vI)
            DO_WIN(1, vJ)
            DO_WIN(2, vI2)
            DO_WIN(3, vJ2)
            DO_WIN(4, vIJ)
#undef DO_WIN

#pragma unroll
            for (int c = 0; c < 4; ++c) {
                float sI = box[0][c], sJ = box[1][c];
                float cross = fmaf(sI * sJ, -inv81, box[4][c]);
                float Iv    = fmaf(sI * sI, -inv81, box[2][c]);
                float Jv    = fmaf(sJ * sJ, -inv81, box[3][c]);
                float den   = fmaf(Iv, Jv, 1e-5f);
                acc += __fdividef(cross * cross, den);
            }
        }
    }

    // Block reduction -> global double atomic; last block finalizes + resets.
#pragma unroll
    for (int o = 16; o; o >>= 1) acc += __shfl_xor_sync(0xffffffffu, acc, o);
    if (lane == 0) wsum[t >> 5] = acc;
    __syncthreads();
    if (t == 0) {
        float bs = 0.f;
#pragma unroll
        for (int w = 0; w < TPB / 32; ++w) bs += wsum[w];
        atomicAdd(&g_acc, (double)bs);
        __threadfence();
        unsigned int done = atomicAdd(&g_cnt, 1u);
        if (done == NBLOCKS - 1) {
            __threadfence();
            double v = *((volatile double*)&g_acc);
            out[0] = (float)(-v * (1.0 / (double)((long long)NB * BH * BW)));
            g_acc = 0.0;          // reset for next graph replay
            g_cnt = 0u;
        }
    }
}

extern "C" void kernel_launch(void* const* d_in, const int* in_sizes, int n_in,
                              void* d_out, int out_size) {
    const float* I = (const float*)d_in[0];
    const float* J = (const float*)d_in[1];
    float* out = (float*)d_out;

    dim3 grid(STRIPS, NB);   // (22, 32) = 704 blocks, single wave
    ncc_main_k<<<grid, TPB>>>(I, J, out);
}